// round 13
// baseline (speedup 1.0000x reference)
#include <cuda_runtime.h>
#include <cuda_bf16.h>
#include <mma.h>
#include <cstdint>

using namespace nvcuda;

#define Bm 512
#define Em 256
#define Am 128
#define Km 6
#define Fm 147
#define AFm 133
#define Hm 128

#define KWI 160          // 147 padded
#define KWO 272          // 133 af + 11 zero + 128 m2a
#define LDA_WI 168
#define LD_128 136
#define LD_144 152

// f32 scratch
__device__ float g_inp [Bm * Em * Hm];
__device__ float g_msgA[Bm * Em * Hm];
__device__ float g_msgB[Bm * Em * Hm];
__device__ int   g_off[Bm];
// pre-split hi/lo bf16 weights, row-major [128][K]
__device__ __align__(16) __nv_bfloat16 g_WiH[128 * KWI];
__device__ __align__(16) __nv_bfloat16 g_WiL[128 * KWI];
__device__ __align__(16) __nv_bfloat16 g_WhH[128 * 128];
__device__ __align__(16) __nv_bfloat16 g_WhL[128 * 128];
__device__ __align__(16) __nv_bfloat16 g_WoH[128 * KWO];
__device__ __align__(16) __nv_bfloat16 g_WoL[128 * KWO];

// write 4 consecutive cols (c..c+3) of row r into hi/lo bf16 smem tiles
__device__ __forceinline__ void wr4(__nv_bfloat16* AH, __nv_bfloat16* AL,
                                    int ldm, int r, int c, float4 v) {
    int o = r * ldm + c;
    __nv_bfloat16 h0 = __float2bfloat16_rn(v.x), h1 = __float2bfloat16_rn(v.y),
                  h2 = __float2bfloat16_rn(v.z), h3 = __float2bfloat16_rn(v.w);
    uint2 hp;
    hp.x = (uint32_t)__bfloat16_as_ushort(h0) | ((uint32_t)__bfloat16_as_ushort(h1) << 16);
    hp.y = (uint32_t)__bfloat16_as_ushort(h2) | ((uint32_t)__bfloat16_as_ushort(h3) << 16);
    *(uint2*)(AH + o) = hp;
    __nv_bfloat16 l0 = __float2bfloat16_rn(v.x - __bfloat162float(h0));
    __nv_bfloat16 l1 = __float2bfloat16_rn(v.y - __bfloat162float(h1));
    __nv_bfloat16 l2 = __float2bfloat16_rn(v.z - __bfloat162float(h2));
    __nv_bfloat16 l3 = __float2bfloat16_rn(v.w - __bfloat162float(h3));
    uint2 lp;
    lp.x = (uint32_t)__bfloat16_as_ushort(l0) | ((uint32_t)__bfloat16_as_ushort(l1) << 16);
    lp.y = (uint32_t)__bfloat16_as_ushort(l2) | ((uint32_t)__bfloat16_as_ushort(l3) << 16);
    *(uint2*)(AL + o) = lp;
}

typedef wmma::fragment<wmma::matrix_a, 16, 16, 16, __nv_bfloat16, wmma::row_major> FragA;
typedef wmma::fragment<wmma::matrix_b, 16, 16, 16, __nv_bfloat16, wmma::col_major> FragB;
typedef wmma::fragment<wmma::accumulator, 16, 16, 16, float> FragC;

// ---------------------------------------------------------------------------
extern "C" __global__ void __launch_bounds__(512) k_scan(const int* __restrict__ ml,
                                                         float* __restrict__ maskbase)
{
    __shared__ int s[512];
    int t = threadIdx.x;
    int v = ml[t];
    s[t] = v;
    __syncthreads();
    for (int off = 1; off < 512; off <<= 1) {
        int u = (t >= off) ? s[t - off] : 0;
        __syncthreads();
        s[t] += u;
        __syncthreads();
    }
    g_off[t] = s[t] - v;
    for (int i = t; i < Bm * Am; i += 512) {
        int b = i >> 7, a = i & 127;
        maskbase[i] = (a < ml[b]) ? 1.0f : 0.0f;
    }
}

// ---------------------------------------------------------------------------
extern "C" __global__ void __launch_bounds__(256) k_tw(const float* __restrict__ Wi,
                                                       const float* __restrict__ Wh,
                                                       const float* __restrict__ Wo)
{
    int idx = blockIdx.x * 256 + threadIdx.x;
    float v; __nv_bfloat16 *ph, *pl; int o;
    if (idx < 128 * KWI) {
        int n = idx / KWI, k = idx - n * KWI;
        v = (k < Fm) ? Wi[n * Fm + k] : 0.f;
        ph = g_WiH; pl = g_WiL; o = idx;
    } else if (idx < 128 * KWI + 128 * 128) {
        int p = idx - 128 * KWI;
        v = Wh[p];
        ph = g_WhH; pl = g_WhL; o = p;
    } else if (idx < 128 * (KWI + 128 + KWO)) {
        int p = idx - 128 * KWI - 128 * 128;
        int n = p / KWO, k = p - n * KWO;
        if (k < AFm)        v = Wo[n * 261 + k];
        else if (k >= 144)  v = Wo[n * 261 + k - 11];
        else                v = 0.f;
        ph = g_WoH; pl = g_WoL; o = p;
    } else return;
    __nv_bfloat16 h = __float2bfloat16_rn(v);
    ph[o] = h;
    pl[o] = __float2bfloat16_rn(v - __bfloat162float(h));
}

// ---------------------------------------------------------------------------
// k_wi: inp = fin @ Wi^T ; msgA = relu(inp).  M=128/block, grid 1024.
// 2x4 warp tiling (warp = 64 rows x 32 cols), fragment epilogue (no smem C).
// ---------------------------------------------------------------------------
#define WI_AH 0
#define WI_AL (128 * LDA_WI)
#define WI_BH (2 * 128 * LDA_WI)
#define WI_BL (3 * 128 * LDA_WI)
#define WI_SMB (4 * 128 * LDA_WI * 2)

extern "C" __global__ void __launch_bounds__(256) k_wi(const float* __restrict__ fin)
{
    extern __shared__ __nv_bfloat16 sm[];
    int tid = threadIdx.x, w = tid >> 5;
    int row0 = blockIdx.x * 128;

    // stage B
    {
        const uint4* sh = (const uint4*)g_WiH;
        const uint4* sl = (const uint4*)g_WiL;
        for (int i = tid; i < 128 * KWI / 8; i += 256) {
            int r = i / (KWI / 8), ch = i - r * (KWI / 8);
            *(uint4*)(sm + WI_BH + r * LDA_WI + ch * 8) = sh[i];
            *(uint4*)(sm + WI_BL + r * LDA_WI + ch * 8) = sl[i];
        }
    }
    // stage A (2 threads/row)
    {
        int r = tid >> 1, h = tid & 1;
        const float* fr = fin + (size_t)(row0 + r) * Fm;
        for (int c = h * 80; c < h * 80 + 80; c += 4) {
            float4 v;
            v.x = (c + 0 < Fm) ? fr[c + 0] : 0.f;
            v.y = (c + 1 < Fm) ? fr[c + 1] : 0.f;
            v.z = (c + 2 < Fm) ? fr[c + 2] : 0.f;
            v.w = (c + 3 < Fm) ? fr[c + 3] : 0.f;
            wr4(sm + WI_AH, sm + WI_AL, LDA_WI, r, c, v);
        }
    }
    __syncthreads();

    int wm = w >> 2, wn = w & 3;      // warp rows [wm*64,+64), cols [wn*32,+32)
    FragC c[4][2];
#pragma unroll
    for (int m = 0; m < 4; m++)
#pragma unroll
        for (int j = 0; j < 2; j++) wmma::fill_fragment(c[m][j], 0.f);

    for (int ks = 0; ks < KWI / 16; ks++) {
        FragA ah[4], al[4];
#pragma unroll
        for (int m = 0; m < 4; m++) {
            const __nv_bfloat16* ap = sm + (wm * 64 + m * 16) * LDA_WI + ks * 16;
            wmma::load_matrix_sync(ah[m], ap + WI_AH, LDA_WI);
            wmma::load_matrix_sync(al[m], ap + WI_AL, LDA_WI);
        }
        FragB bh[2], bl[2];
#pragma unroll
        for (int j = 0; j < 2; j++) {
            const __nv_bfloat16* bp = sm + (wn * 32 + j * 16) * LDA_WI + ks * 16;
            wmma::load_matrix_sync(bh[j], bp + WI_BH, LDA_WI);
            wmma::load_matrix_sync(bl[j], bp + WI_BL, LDA_WI);
        }
#pragma unroll
        for (int m = 0; m < 4; m++)
#pragma unroll
            for (int j = 0; j < 2; j++) {
                wmma::mma_sync(c[m][j], ah[m], bh[j], c[m][j]);
                wmma::mma_sync(c[m][j], ah[m], bl[j], c[m][j]);
                wmma::mma_sync(c[m][j], al[m], bh[j], c[m][j]);
            }
    }

    // fragment epilogue: inp = c ; msgA = relu(c)
#pragma unroll
    for (int m = 0; m < 4; m++)
#pragma unroll
        for (int j = 0; j < 2; j++) {
            size_t off = (size_t)(row0 + wm * 64 + m * 16) * Hm + wn * 32 + j * 16;
            wmma::store_matrix_sync(g_inp + off, c[m][j], Hm, wmma::mem_row_major);
#pragma unroll
            for (int e = 0; e < c[m][j].num_elements; e++)
                c[m][j].x[e] = fmaxf(c[m][j].x[e], 0.f);
            wmma::store_matrix_sync(g_msgA + off, c[m][j], Hm, wmma::mem_row_major);
        }
}

// ---------------------------------------------------------------------------
// k_mp: agg = gather6(msg_in); msg_out = relu(inp + agg @ Wh^T).
// M=64/block, grid 2048, 2 blocks/SM. 2Mx4N warp tiling (warp = 32x32).
// ---------------------------------------------------------------------------
#define MP_AH 0
#define MP_AL (64 * LD_128)
#define MP_BH (2 * 64 * LD_128)
#define MP_BL (2 * 64 * LD_128 + 128 * LD_128)
#define MP_SMB ((2 * 64 * LD_128 + 2 * 128 * LD_128) * 2)

extern "C" __global__ void __launch_bounds__(256, 2) k_mp(const int* __restrict__ mapping, int dir)
{
    const float* msg_in = dir ? g_msgB : g_msgA;
    float* msg_out = dir ? g_msgA : g_msgB;

    extern __shared__ __nv_bfloat16 sm[];
    int tid = threadIdx.x, w = tid >> 5;
    int row0 = blockIdx.x * 64;
    int bmol = blockIdx.x >> 2;

    // stage B (full 128x128 hi/lo)
    {
        const uint4* sh = (const uint4*)g_WhH;
        const uint4* sl = (const uint4*)g_WhL;
        for (int i = tid; i < 128 * 128 / 8; i += 256) {
            int r = i >> 4, ch = i & 15;
            *(uint4*)(sm + MP_BH + r * LD_128 + ch * 8) = sh[i];
            *(uint4*)(sm + MP_BL + r * LD_128 + ch * 8) = sl[i];
        }
    }
    // gather (4 threads/row, 32 cols each)
    {
        int r = tid >> 2, seg = (tid & 3) * 32;
        int gr = row0 + r;
        const int* mp = mapping + (size_t)gr * Km;
        int i0 = mp[0], i1 = mp[1], i2 = mp[2], i3 = mp[3], i4 = mp[4], i5 = mp[5];
        const float* mb = msg_in + (size_t)bmol * Em * Hm + seg;
        const float4* p0 = (const float4*)(mb + (size_t)i0 * Hm);
        const float4* p1 = (const float4*)(mb + (size_t)i1 * Hm);
        const float4* p2 = (const float4*)(mb + (size_t)i2 * Hm);
        const float4* p3 = (const float4*)(mb + (size_t)i3 * Hm);
        const float4* p4 = (const float4*)(mb + (size_t)i4 * Hm);
        const float4* p5 = (const float4*)(mb + (size_t)i5 * Hm);
#pragma unroll
        for (int j = 0; j < 8; j++) {
            float4 a = p0[j], b = p1[j], c = p2[j], d = p3[j], e = p4[j], f = p5[j];
            float4 s = make_float4(a.x + b.x + c.x + d.x + e.x + f.x,
                                   a.y + b.y + c.y + d.y + e.y + f.y,
                                   a.z + b.z + c.z + d.z + e.z + f.z,
                                   a.w + b.w + c.w + d.w + e.w + f.w);
            wr4(sm + MP_AH, sm + MP_AL, LD_128, r, seg + 4 * j, s);
        }
    }
    __syncthreads();

    int wm = w >> 2, wn = w & 3;      // warp rows [wm*32,+32), cols [wn*32,+32)
    FragC c[2][2];
#pragma unroll
    for (int m = 0; m < 2; m++)
#pragma unroll
        for (int j = 0; j < 2; j++) wmma::fill_fragment(c[m][j], 0.f);

    for (int ks = 0; ks < 8; ks++) {
        FragA ah[2], al[2];
#pragma unroll
        for (int m = 0; m < 2; m++) {
            const __nv_bfloat16* ap = sm + (wm * 32 + m * 16) * LD_128 + ks * 16;
            wmma::load_matrix_sync(ah[m], ap + MP_AH, LD_128);
            wmma::load_matrix_sync(al[m], ap + MP_AL, LD_128);
        }
        FragB bh[2], bl[2];
#pragma unroll
        for (int j = 0; j < 2; j++) {
            const __nv_bfloat16* bp = sm + (wn * 32 + j * 16) * LD_128 + ks * 16;
            wmma::load_matrix_sync(bh[j], bp + MP_BH, LD_128);
            wmma::load_matrix_sync(bl[j], bp + MP_BL, LD_128);
        }
#pragma unroll
        for (int m = 0; m < 2; m++)
#pragma unroll
            for (int j = 0; j < 2; j++) {
                wmma::mma_sync(c[m][j], ah[m], bh[j], c[m][j]);
                wmma::mma_sync(c[m][j], ah[m], bl[j], c[m][j]);
                wmma::mma_sync(c[m][j], al[m], bh[j], c[m][j]);
            }
    }

    // fragment epilogue: msg_out = relu(inp + c)
#pragma unroll
    for (int m = 0; m < 2; m++)
#pragma unroll
        for (int j = 0; j < 2; j++) {
            size_t off = (size_t)(row0 + wm * 32 + m * 16) * Hm + wn * 32 + j * 16;
            FragC fi;
            wmma::load_matrix_sync(fi, g_inp + off, Hm, wmma::mem_row_major);
#pragma unroll
            for (int e = 0; e < fi.num_elements; e++)
                c[m][j].x[e] = fmaxf(c[m][j].x[e] + fi.x[e], 0.f);
            wmma::store_matrix_sync(msg_out + off, c[m][j], Hm, wmma::mem_row_major);
        }
}

// ---------------------------------------------------------------------------
// k_out: unchanged from R8 (passing): cat = [af | 0*11 | m2a];
// atoms_h = relu(cat @ WoT + bo); scatter. grid 512.
// ---------------------------------------------------------------------------
#define KO_A1H 0
#define KO_A1L (128 * LD_144)
#define KO_A2H (2 * 128 * LD_144)
#define KO_A2L (2 * 128 * LD_144 + 128 * LD_128)
#define KO_BH  (2 * 128 * LD_144 + 2 * 128 * LD_128)
#define KO_BL  (3 * 128 * LD_144 + 2 * 128 * LD_128)
#define KO_BIAS (4 * 128 * LD_144 + 2 * 128 * LD_128)
#define KO_SMB ((4 * 128 * LD_144 + 2 * 128 * LD_128) * 2 + 512)

__device__ __forceinline__ void ko_mma_tile(const __nv_bfloat16* AH, const __nv_bfloat16* AL, int ldA,
                                            const __nv_bfloat16* BH, const __nv_bfloat16* BL, int ldB,
                                            int nks, int w, FragC c[8]) {
    for (int ks = 0; ks < nks; ks++) {
        FragA ah, al;
        wmma::load_matrix_sync(ah, AH + w * 16 * ldA + ks * 16, ldA);
        wmma::load_matrix_sync(al, AL + w * 16 * ldA + ks * 16, ldA);
#pragma unroll
        for (int nt = 0; nt < 8; nt++) {
            FragB bh, bl;
            wmma::load_matrix_sync(bh, BH + nt * 16 * ldB + ks * 16, ldB);
            wmma::load_matrix_sync(bl, BL + nt * 16 * ldB + ks * 16, ldB);
            wmma::mma_sync(c[nt], ah, bh, c[nt]);
            wmma::mma_sync(c[nt], ah, bl, c[nt]);
            wmma::mma_sync(c[nt], al, bh, c[nt]);
        }
    }
}

extern "C" __global__ void __launch_bounds__(256) k_out(const float* __restrict__ af,
                                                        const int* __restrict__ a2b,
                                                        const float* __restrict__ bo,
                                                        const int* __restrict__ ml,
                                                        float* __restrict__ out)
{
    extern __shared__ __nv_bfloat16 sm[];
    int tid = threadIdx.x, w = tid >> 5;
    int b = blockIdx.x;
    int row0 = b * 128;

    if (tid < 128) ((float*)(sm + KO_BIAS))[tid] = bo[tid];

    int r = tid >> 1, h = tid & 1, hb = h * 64;
    {
        int gr = row0 + r;
        const int* gi = a2b + (size_t)gr * Km;
        int i0 = gi[0], i1 = gi[1], i2 = gi[2], i3 = gi[3], i4 = gi[4], i5 = gi[5];
        const float* mb = g_msgA + (size_t)b * Em * Hm + hb;
        const float4* p0 = (const float4*)(mb + (size_t)i0 * Hm);
        const float4* p1 = (const float4*)(mb + (size_t)i1 * Hm);
        const float4* p2 = (const float4*)(mb + (size_t)i2 * Hm);
        const float4* p3 = (const float4*)(mb + (size_t)i3 * Hm);
        const float4* p4 = (const float4*)(mb + (size_t)i4 * Hm);
        const float4* p5 = (const float4*)(mb + (size_t)i5 * Hm);
#pragma unroll
        for (int j = 0; j < 16; j++) {
            float4 a = p0[j], bb = p1[j], c = p2[j], d = p3[j], e = p4[j], f = p5[j];
            float4 s = make_float4(a.x + bb.x + c.x + d.x + e.x + f.x,
                                   a.y + bb.y + c.y + d.y + e.y + f.y,
                                   a.z + bb.z + c.z + d.z + e.z + f.z,
                                   a.w + bb.w + c.w + d.w + e.w + f.w);
            wr4(sm + KO_A2H, sm + KO_A2L, LD_128, r, hb + 4 * j, s);
        }
    }
    {
        const float* ar = af + (size_t)(row0 + r) * AFm;
        for (int c = h * 72; c < h * 72 + 72; c += 4) {
            float4 v;
            v.x = (c + 0 < AFm) ? ar[c + 0] : 0.f;
            v.y = (c + 1 < AFm) ? ar[c + 1] : 0.f;
            v.z = (c + 2 < AFm) ? ar[c + 2] : 0.f;
            v.w = (c + 3 < AFm) ? ar[c + 3] : 0.f;
            wr4(sm + KO_A1H, sm + KO_A1L, LD_144, r, c, v);
        }
    }
    {
        const uint4* sh = (const uint4*)g_WoH;
        const uint4* sl = (const uint4*)g_WoL;
        for (int i = tid; i < 128 * 18; i += 256) {
            int rr = i / 18, ch = i - rr * 18;
            uint4 vh = sh[rr * (KWO / 8) + ch];
            uint4 vl = sl[rr * (KWO / 8) + ch];
            *(uint4*)(sm + KO_BH + rr * LD_144 + ch * 8) = vh;
            *(uint4*)(sm + KO_BL + rr * LD_144 + ch * 8) = vl;
        }
    }
    __syncthreads();

    FragC c[8];
#pragma unroll
    for (int nt = 0; nt < 8; nt++) wmma::fill_fragment(c[nt], 0.f);
    ko_mma_tile(sm + KO_A1H, sm + KO_A1L, LD_144, sm + KO_BH, sm + KO_BL, LD_144, 9, w, c);
    __syncthreads();

    {
        const uint4* sh = (const uint4*)g_WoH;
        const uint4* sl = (const uint4*)g_WoL;
        for (int i = tid; i < 128 * 16; i += 256) {
            int rr = i >> 4, ch = i & 15;
            uint4 vh = sh[rr * (KWO / 8) + 18 + ch];
            uint4 vl = sl[rr * (KWO / 8) + 18 + ch];
            *(uint4*)(sm + KO_BH + rr * LD_144 + ch * 8) = vh;
            *(uint4*)(sm + KO_BL + rr * LD_144 + ch * 8) = vl;
        }
    }
    __syncthreads();

    ko_mma_tile(sm + KO_A2H, sm + KO_A2L, LD_128, sm + KO_BH, sm + KO_BL, LD_144, 8, w, c);
    __syncthreads();

    float* Cs = (float*)sm;
#pragma unroll
    for (int nt = 0; nt < 8; nt++)
        wmma::store_matrix_sync(Cs + w * 16 * LD_128 + nt * 16, c[nt], LD_128, wmma::mem_row_major);
    __syncthreads();

    {
        int len = ml[b];
        if (r < len) {
            const float* cr = Cs + r * LD_128 + hb;
            const float* bs = (const float*)(sm + KO_BIAS) + hb;
            float4* po = (float4*)(out + (size_t)(g_off[b] + r) * Hm + hb);
#pragma unroll
            for (int q = 0; q < 16; q++)
                po[q] = make_float4(fmaxf(cr[4 * q + 0] + bs[4 * q + 0], 0.f),
                                    fmaxf(cr[4 * q + 1] + bs[4 * q + 1], 0.f),
                                    fmaxf(cr[4 * q + 2] + bs[4 * q + 2], 0.f),
                                    fmaxf(cr[4 * q + 3] + bs[4 * q + 3], 0.f));
        }
    }
}

// ---------------------------------------------------------------------------
extern "C" void kernel_launch(void* const* d_in, const int* in_sizes, int n_in,
                              void* d_out, int out_size)
{
    const float* af      = (const float*)d_in[0];
    const float* fin     = (const float*)d_in[1];
    const int*   a2b     = (const int*)d_in[2];
    const int*   mapping = (const int*)d_in[3];
    const int*   ml      = (const int*)d_in[5];
    const float* Wi      = (const float*)d_in[6];
    const float* Wh      = (const float*)d_in[7];
    const float* Wo      = (const float*)d_in[8];
    const float* bo      = (const float*)d_in[9];
    float* out = (float*)d_out;
    float* maskbase = out + (size_t)out_size - (size_t)Bm * Am;

    cudaFuncSetAttribute(k_wi,  cudaFuncAttributeMaxDynamicSharedMemorySize, WI_SMB);
    cudaFuncSetAttribute(k_mp,  cudaFuncAttributeMaxDynamicSharedMemorySize, MP_SMB);
    cudaFuncSetAttribute(k_out, cudaFuncAttributeMaxDynamicSharedMemorySize, KO_SMB);

    k_scan<<<1, 512>>>(ml, maskbase);
    k_tw<<<(128 * (KWI + 128 + KWO) + 255) / 256, 256>>>(Wi, Wh, Wo);
    k_wi<<<1024, 256, WI_SMB>>>(fin);
    k_mp<<<2048, 256, MP_SMB>>>(mapping, 0);   // msgA -> msgB
    k_mp<<<2048, 256, MP_SMB>>>(mapping, 1);   // msgB -> msgA
    k_out<<<512, 256, KO_SMB>>>(af, a2b, bo, ml, out);
}